// round 2
// baseline (speedup 1.0000x reference)
#include <cuda_runtime.h>
#include <math.h>

// Problem constants
#define BB 32
#define SS 512
#define HH 2048
#define NHH 8
#define HD 256
#define MR (BB*SS)           // 16384 rows
#define H3 (3*HH)            // 6144
#define H4 (4*HH)            // 8192
#define NHEADS (BB*NHH)      // 256
#define NSROWS (NHEADS*SS)   // 131072 softmax rows

// ---------------- scratch (device globals; allocation-free rule) -------------
__device__ float g_x  [ (size_t)MR*HH   ];   // 134 MB  x = emb + pe gather
__device__ float g_qkv[ (size_t)MR*H3   ];   // 402 MB
__device__ float g_sc [ (size_t)NHEADS*SS*SS ]; // 268 MB scores
__device__ float g_o  [ (size_t)MR*HH   ];   // attn context (pre out_proj); reused for pr
__device__ float g_h1 [ (size_t)MR*HH   ];
__device__ float g_h2 [ (size_t)MR*HH   ];
__device__ float g_t1 [ (size_t)MR*HH   ];
__device__ float g_t2 [ (size_t)MR*HH   ];
__device__ float g_mid[ (size_t)MR*H4   ];   // 536 MB FFN mid

// ---------------- elementwise kernels ----------------------------------------

// x[b,s,:] = emb[b,s,:] + pe[idx[b,s],:]   (vectorized float4)
__global__ void gather_pe_kernel(const float* __restrict__ emb,
                                 const float* __restrict__ pe,
                                 const int*   __restrict__ idx,
                                 float* __restrict__ x)
{
    long i = (long)blockIdx.x * blockDim.x + threadIdx.x;   // over MR*HH/4
    const long n4 = (long)MR * HH / 4;
    if (i >= n4) return;
    long row = i / (HH/4);
    long c4  = i - row * (HH/4);
    float4 e = ((const float4*)emb)[i];
    const float4* p = (const float4*)(pe + (long)idx[row]*HH);
    float4 pv = p[c4];
    float4 r; r.x=e.x+pv.x; r.y=e.y+pv.y; r.z=e.z+pv.z; r.w=e.w+pv.w;
    ((float4*)x)[i] = r;
}

// LayerNorm over last dim (2048); one 256-thread block per row
__global__ void ln_kernel(const float* __restrict__ in,
                          const float* __restrict__ g,
                          const float* __restrict__ b,
                          float* __restrict__ out)
{
    __shared__ float sh[8];
    long row = blockIdx.x;
    const float* x = in + row * (long)HH;
    int t = threadIdx.x;
    float v[8];
    float s = 0.f;
    #pragma unroll
    for (int i = 0; i < 8; i++) { v[i] = x[t + i*256]; s += v[i]; }
    #pragma unroll
    for (int o = 16; o > 0; o >>= 1) s += __shfl_xor_sync(0xffffffffu, s, o);
    if ((t & 31) == 0) sh[t >> 5] = s;
    __syncthreads();
    float tot = sh[0]+sh[1]+sh[2]+sh[3]+sh[4]+sh[5]+sh[6]+sh[7];
    float mean = tot * (1.f/HH);
    __syncthreads();
    float sq = 0.f;
    #pragma unroll
    for (int i = 0; i < 8; i++) { float d = v[i]-mean; sq += d*d; }
    #pragma unroll
    for (int o = 16; o > 0; o >>= 1) sq += __shfl_xor_sync(0xffffffffu, sq, o);
    if ((t & 31) == 0) sh[t >> 5] = sq;
    __syncthreads();
    float tot2 = sh[0]+sh[1]+sh[2]+sh[3]+sh[4]+sh[5]+sh[6]+sh[7];
    float rstd = rsqrtf(tot2 * (1.f/HH) + 1e-5f);
    float* orow = out + row * (long)HH;
    #pragma unroll
    for (int i = 0; i < 8; i++) {
        int c = t + i*256;
        orow[c] = (v[i]-mean)*rstd*g[c] + b[c];
    }
}

// row L2-normalize (last dim 2048)
__global__ void l2norm_kernel(const float* __restrict__ in, float* __restrict__ out)
{
    __shared__ float sh[8];
    long row = blockIdx.x;
    const float* x = in + row * (long)HH;
    int t = threadIdx.x;
    float v[8];
    float sq = 0.f;
    #pragma unroll
    for (int i = 0; i < 8; i++) { v[i] = x[t + i*256]; sq += v[i]*v[i]; }
    #pragma unroll
    for (int o = 16; o > 0; o >>= 1) sq += __shfl_xor_sync(0xffffffffu, sq, o);
    if ((t & 31) == 0) sh[t >> 5] = sq;
    __syncthreads();
    float tot = sh[0]+sh[1]+sh[2]+sh[3]+sh[4]+sh[5]+sh[6]+sh[7];
    float inv = 1.f / fmaxf(sqrtf(tot), 1e-12f);
    float* orow = out + row * (long)HH;
    #pragma unroll
    for (int i = 0; i < 8; i++) { int c = t + i*256; orow[c] = v[i]*inv; }
}

// softmax over rows of 512; one warp per row, 8 warps/block
__global__ void softmax_kernel(float* __restrict__ s)
{
    long warp = ((long)blockIdx.x * blockDim.x + threadIdx.x) >> 5;
    int lane = threadIdx.x & 31;
    if (warp >= (long)NSROWS) return;
    float* row = s + warp * (long)SS;
    float vals[16];
    float mx = -1e30f;
    #pragma unroll
    for (int i = 0; i < 16; i++) { vals[i] = row[lane + i*32]; mx = fmaxf(mx, vals[i]); }
    #pragma unroll
    for (int o = 16; o > 0; o >>= 1) mx = fmaxf(mx, __shfl_xor_sync(0xffffffffu, mx, o));
    float sum = 0.f;
    #pragma unroll
    for (int i = 0; i < 16; i++) { vals[i] = __expf(vals[i]-mx); sum += vals[i]; }
    #pragma unroll
    for (int o = 16; o > 0; o >>= 1) sum += __shfl_xor_sync(0xffffffffu, sum, o);
    float inv = 1.f / sum;
    #pragma unroll
    for (int i = 0; i < 16; i++) row[lane + i*32] = vals[i]*inv;
}

// ---------------- tiled fp32 GEMM ---------------------------------------------
// C[M,N] = act( alpha * A@op(B) + bias ) (+ R)
// BT=true : op(B)=B^T, B stored [N,K] (weight layout / Q@K^T)
// BT=false: op(B)=B,   B stored [K,N] (A@V)
// Batched via blockIdx.z = zb*8+zh with affine offsets.
// Tile 128x128x8, 256 threads, 8x8 per thread.
template<bool BT, int ACT, bool RESID>
__global__ void __launch_bounds__(256, 2) gemm_kernel(
    const float* __restrict__ A, const float* __restrict__ Bm,
    const float* __restrict__ bias, const float* __restrict__ R,
    float* __restrict__ C,
    int K, int lda, int ldb, int ldc,
    long offA1, long offA2, long offB1, long offB2, long offC1, long offC2,
    float alpha)
{
    __shared__ __align__(16) float As[8][128];
    __shared__ __align__(16) float Bs[8][128];

    int z = blockIdx.z;
    int zb = z >> 3, zh = z & 7;
    A  += zb*offA1 + zh*offA2;
    Bm += zb*offB1 + zh*offB2;
    C  += zb*offC1 + zh*offC2;

    int tid  = threadIdx.x;
    long bm0 = (long)blockIdx.y * 128;
    long bn0 = (long)blockIdx.x * 128;

    int arow = tid >> 1;            // 0..127
    int acol = (tid & 1) << 2;      // 0 or 4
    int bkrow = tid >> 5;           // NN: 0..7
    int bncol = (tid & 31) << 2;    // NN: 0..124

    const float* Aptr = A + (bm0 + arow) * (long)lda + acol;
    const float* Bptr = BT ? (Bm + (bn0 + arow) * (long)ldb + acol)
                           : (Bm + (long)bkrow * ldb + bn0 + bncol);

    float acc[8][8];
    #pragma unroll
    for (int i = 0; i < 8; i++)
        #pragma unroll
        for (int j = 0; j < 8; j++) acc[i][j] = 0.f;

    int mth = (tid >> 4) << 3;
    int nth = (tid & 15) << 3;

    for (int k0 = 0; k0 < K; k0 += 8) {
        float4 av = *(const float4*)Aptr;
        As[acol+0][arow] = av.x; As[acol+1][arow] = av.y;
        As[acol+2][arow] = av.z; As[acol+3][arow] = av.w;
        if (BT) {
            float4 bv = *(const float4*)Bptr;
            Bs[acol+0][arow] = bv.x; Bs[acol+1][arow] = bv.y;
            Bs[acol+2][arow] = bv.z; Bs[acol+3][arow] = bv.w;
        } else {
            float4 bv = *(const float4*)Bptr;
            *(float4*)&Bs[bkrow][bncol] = bv;
        }
        Aptr += 8;
        Bptr += BT ? 8 : 8 * (long)ldb;
        __syncthreads();
        #pragma unroll
        for (int kk = 0; kk < 8; kk++) {
            float ar[8], br[8];
            *(float4*)&ar[0] = *(const float4*)&As[kk][mth];
            *(float4*)&ar[4] = *(const float4*)&As[kk][mth+4];
            *(float4*)&br[0] = *(const float4*)&Bs[kk][nth];
            *(float4*)&br[4] = *(const float4*)&Bs[kk][nth+4];
            #pragma unroll
            for (int i = 0; i < 8; i++)
                #pragma unroll
                for (int j = 0; j < 8; j++)
                    acc[i][j] += ar[i]*br[j];
        }
        __syncthreads();
    }

    #pragma unroll
    for (int i = 0; i < 8; i++) {
        long row = bm0 + mth + i;
        float* crow = C + row * (long)ldc;
        const float* rrow = RESID ? (R + row * (long)ldc) : (const float*)0;
        #pragma unroll
        for (int j = 0; j < 8; j++) {
            long col = bn0 + nth + j;
            float v = acc[i][j] * alpha;
            if (bias) v += bias[col];
            if (ACT == 1) v = 0.5f*v*(1.f + erff(v*0.70710678118654752f));  // exact GELU
            else if (ACT == 2) v = fmaxf(v, 0.f);
            if (RESID) v += rrow[col];
            crow[col] = v;
        }
    }
}

// ---------------- host orchestration ------------------------------------------
extern "C" void kernel_launch(void* const* d_in, const int* in_sizes, int n_in,
                              void* d_out, int out_size)
{
    (void)in_sizes; (void)n_in; (void)out_size;
    const float* emb  = (const float*)d_in[0];
    const int*   tidx = (const int*)  d_in[1];
    const float* pe   = (const float*)d_in[2];
    const float* inw  = (const float*)d_in[3];
    const float* inb  = (const float*)d_in[4];
    const float* ow   = (const float*)d_in[5];
    const float* ob   = (const float*)d_in[6];
    const float* ln1g = (const float*)d_in[7];
    const float* ln1b = (const float*)d_in[8];
    const float* f1w  = (const float*)d_in[9];
    const float* f1b  = (const float*)d_in[10];
    const float* f2w  = (const float*)d_in[11];
    const float* f2b  = (const float*)d_in[12];
    const float* ln2g = (const float*)d_in[13];
    const float* ln2b = (const float*)d_in[14];
    const float* te1w = (const float*)d_in[15];
    const float* te1b = (const float*)d_in[16];
    const float* te2w = (const float*)d_in[17];
    const float* te2b = (const float*)d_in[18];
    const float* pr1w = (const float*)d_in[19];
    const float* pr1b = (const float*)d_in[20];
    const float* pr2w = (const float*)d_in[21];
    const float* pr2b = (const float*)d_in[22];
    float* out = (float*)d_out;

    float *x, *qkv, *sc, *o, *h1, *h2, *t1, *t2, *mid;
    cudaGetSymbolAddress((void**)&x,   g_x);
    cudaGetSymbolAddress((void**)&qkv, g_qkv);
    cudaGetSymbolAddress((void**)&sc,  g_sc);
    cudaGetSymbolAddress((void**)&o,   g_o);
    cudaGetSymbolAddress((void**)&h1,  g_h1);
    cudaGetSymbolAddress((void**)&h2,  g_h2);
    cudaGetSymbolAddress((void**)&t1,  g_t1);
    cudaGetSymbolAddress((void**)&t2,  g_t2);
    cudaGetSymbolAddress((void**)&mid, g_mid);

    const long QS = (long)SS * H3;        // per-batch stride inside qkv: 512*6144
    const long SC = (long)SS * SS;        // 262144 per head

    // 1) x = emb + pe[idx]
    gather_pe_kernel<<<(MR*(HH/4) + 255)/256, 256>>>(emb, pe, tidx, x);

    // 2) qkv = x @ in_proj_w^T + b   [16384 x 6144], K=2048
    gemm_kernel<true,0,false><<<dim3(H3/128, MR/128, 1), 256>>>(
        x, inw, inb, 0, qkv, HH, HH, HH, H3, 0,0,0,0,0,0, 1.f);

    // 3) scores = (Q @ K^T) / 16   batched over 256 heads  [512 x 512], K=256
    gemm_kernel<true,0,false><<<dim3(SS/128, SS/128, NHEADS), 256>>>(
        qkv, qkv + HH, 0, 0, sc, HD, H3, H3, SS,
        QS, HD, QS, HD, 8*SC, SC, 0.0625f);

    // 4) softmax rows
    softmax_kernel<<<NSROWS/8, 256>>>(sc);

    // 5) o = A @ V   [512 x 256], K=512  (NN)
    gemm_kernel<false,0,false><<<dim3(HD/128, SS/128, NHEADS), 256>>>(
        sc, qkv + 2*HH, 0, 0, o, SS, SS, H3, HH,
        8*SC, SC, QS, HD, (long)SS*HH, HD, 1.f);

    // 6) t1 = o @ out_proj_w^T + b + emb   (residual fused)
    gemm_kernel<true,0,true><<<dim3(HH/128, MR/128, 1), 256>>>(
        o, ow, ob, emb, t1, HH, HH, HH, HH, 0,0,0,0,0,0, 1.f);

    // 7) h1 = LN(t1)
    ln_kernel<<<MR, 256>>>(t1, ln1g, ln1b, h1);

    // 8) mid = gelu(h1 @ ffn_w1^T + b1)  [16384 x 8192], K=2048
    gemm_kernel<true,1,false><<<dim3(H4/128, MR/128, 1), 256>>>(
        h1, f1w, f1b, 0, mid, HH, HH, HH, H4, 0,0,0,0,0,0, 1.f);

    // 9) t2 = mid @ ffn_w2^T + b2 + h1   [16384 x 2048], K=8192
    gemm_kernel<true,0,true><<<dim3(HH/128, MR/128, 1), 256>>>(
        mid, f2w, f2b, h1, t2, H4, H4, H4, HH, 0,0,0,0,0,0, 1.f);

    // 10) h2 = LN(t2)
    ln_kernel<<<MR, 256>>>(t2, ln2g, ln2b, h2);

    // 11) t1 = relu(h2 @ te_w1^T + b1)
    gemm_kernel<true,2,false><<<dim3(HH/128, MR/128, 1), 256>>>(
        h2, te1w, te1b, 0, t1, HH, HH, HH, HH, 0,0,0,0,0,0, 1.f);

    // 12) t2 = t1 @ te_w2^T + b2
    gemm_kernel<true,0,false><<<dim3(HH/128, MR/128, 1), 256>>>(
        t1, te2w, te2b, 0, t2, HH, HH, HH, HH, 0,0,0,0,0,0, 1.f);

    // 13) t1 = relu(t2 @ pr_w1^T + b1)
    gemm_kernel<true,2,false><<<dim3(HH/128, MR/128, 1), 256>>>(
        t2, pr1w, pr1b, 0, t1, HH, HH, HH, HH, 0,0,0,0,0,0, 1.f);

    // 14) o = t1 @ pr_w2^T + b2   (reuse o as pr buffer)
    gemm_kernel<true,0,false><<<dim3(HH/128, MR/128, 1), 256>>>(
        t1, pr2w, pr2b, 0, o, HH, HH, HH, HH, 0,0,0,0,0,0, 1.f);

    // 15) out = pr / max(||pr||, 1e-12)
    l2norm_kernel<<<MR, 256>>>(o, out);
}

// round 4
// speedup vs baseline: 3.5238x; 3.5238x over previous
#include <cuda_runtime.h>
#include <cuda_bf16.h>
#include <math.h>
#include <stdint.h>

#define BB 32
#define SS 512
#define HH 2048
#define NHH 8
#define HD 256
#define MR (BB*SS)           // 16384
#define H3 (3*HH)            // 6144
#define H4 (4*HH)            // 8192
#define NHEADS (BB*NHH)      // 256
#define NSROWS (NHEADS*SS)
#define SCH ((long)SS*SS)
#define QSTR ((long)SS*H3)
#define VTS ((long)HD*SS)

// ---------------- scratch (device globals) ------------------------------
__device__ __align__(16) float g_sc [(size_t)NHEADS*SS*SS];   // fp32 scores
__device__ __align__(16) float g_t1 [(size_t)MR*HH];
__device__ __align__(16) float g_t2 [(size_t)MR*HH];
__device__ __align__(16) float g_h1 [(size_t)MR*HH];
// bf16 hi/lo pools
__device__ __align__(16) __nv_bfloat16 g_pAh[(size_t)MR*H4];
__device__ __align__(16) __nv_bfloat16 g_pAl[(size_t)MR*H4];
__device__ __align__(16) __nv_bfloat16 g_pBh[(size_t)NHEADS*SS*SS];
__device__ __align__(16) __nv_bfloat16 g_pBl[(size_t)NHEADS*SS*SS];
__device__ __align__(16) __nv_bfloat16 g_vh [(size_t)MR*HH];
__device__ __align__(16) __nv_bfloat16 g_vl [(size_t)MR*HH];
__device__ __align__(16) __nv_bfloat16 g_wh [(size_t)H4*HH];
__device__ __align__(16) __nv_bfloat16 g_wl [(size_t)H4*HH];

// ---------------- helpers ------------------------------------------------
__device__ __forceinline__ void bsplit(float v, __nv_bfloat16& h, __nv_bfloat16& l){
    h = __float2bfloat16(v);
    l = __float2bfloat16(v - __bfloat162float(h));
}
__device__ __forceinline__ void cpa16(uint32_t s, const void* g){
    asm volatile("cp.async.cg.shared.global [%0], [%1], 16;\n" :: "r"(s), "l"(g));
}
__device__ __forceinline__ void ldsm4(uint32_t addr, uint32_t* r){
    asm volatile("ldmatrix.sync.aligned.m8n8.x4.shared.b16 {%0,%1,%2,%3}, [%4];\n"
        : "=r"(r[0]),"=r"(r[1]),"=r"(r[2]),"=r"(r[3]) : "r"(addr));
}
__device__ __forceinline__ void mma16816(float* d, const uint32_t* a, const uint32_t* b){
    asm volatile("mma.sync.aligned.m16n8k16.row.col.f32.bf16.bf16.f32 "
        "{%0,%1,%2,%3}, {%4,%5,%6,%7}, {%8,%9}, {%0,%1,%2,%3};\n"
        : "+f"(d[0]),"+f"(d[1]),"+f"(d[2]),"+f"(d[3])
        : "r"(a[0]),"r"(a[1]),"r"(a[2]),"r"(a[3]), "r"(b[0]),"r"(b[1]));
}

// ---------------- elementwise kernels ------------------------------------
// x = emb + pe[idx]  -> bf16 hi/lo
__global__ void gather_pe_split(const float* __restrict__ emb,
                                const float* __restrict__ pe,
                                const int*   __restrict__ idx,
                                __nv_bfloat16* __restrict__ xh,
                                __nv_bfloat16* __restrict__ xl)
{
    long i = (long)blockIdx.x * blockDim.x + threadIdx.x;
    const long n4 = (long)MR * HH / 4;
    if (i >= n4) return;
    long row = i / (HH/4);
    long c4  = i - row * (HH/4);
    float4 e = ((const float4*)emb)[i];
    const float4* p = (const float4*)(pe + (long)idx[row]*HH);
    float4 pv = p[c4];
    float v[4] = {e.x+pv.x, e.y+pv.y, e.z+pv.z, e.w+pv.w};
    __nv_bfloat16 h[4], l[4];
    #pragma unroll
    for (int j = 0; j < 4; j++) bsplit(v[j], h[j], l[j]);
    ((__nv_bfloat162*)xh)[2*i]   = __nv_bfloat162(h[0],h[1]);
    ((__nv_bfloat162*)xh)[2*i+1] = __nv_bfloat162(h[2],h[3]);
    ((__nv_bfloat162*)xl)[2*i]   = __nv_bfloat162(l[0],l[1]);
    ((__nv_bfloat162*)xl)[2*i+1] = __nv_bfloat162(l[2],l[3]);
}

// weight split fp32 -> bf16 hi/lo
__global__ void split_kernel(const float* __restrict__ x,
                             __nv_bfloat16* __restrict__ hi,
                             __nv_bfloat16* __restrict__ lo, long n4)
{
    long i = (long)blockIdx.x * blockDim.x + threadIdx.x;
    if (i >= n4) return;
    float4 v = ((const float4*)x)[i];
    __nv_bfloat16 h[4], l[4];
    bsplit(v.x,h[0],l[0]); bsplit(v.y,h[1],l[1]);
    bsplit(v.z,h[2],l[2]); bsplit(v.w,h[3],l[3]);
    ((__nv_bfloat162*)hi)[2*i]   = __nv_bfloat162(h[0],h[1]);
    ((__nv_bfloat162*)hi)[2*i+1] = __nv_bfloat162(h[2],h[3]);
    ((__nv_bfloat162*)lo)[2*i]   = __nv_bfloat162(l[0],l[1]);
    ((__nv_bfloat162*)lo)[2*i+1] = __nv_bfloat162(l[2],l[3]);
}

// LayerNorm; writes optional fp32 + bf16 hi/lo
__global__ void ln_split_kernel(const float* __restrict__ in,
                                const float* __restrict__ g,
                                const float* __restrict__ b,
                                float* __restrict__ of,
                                __nv_bfloat16* __restrict__ oh,
                                __nv_bfloat16* __restrict__ ol)
{
    __shared__ float sh[8];
    long row = blockIdx.x;
    const float* x = in + row * (long)HH;
    int t = threadIdx.x;
    float v[8];
    float s = 0.f;
    #pragma unroll
    for (int i = 0; i < 8; i++) { v[i] = x[t + i*256]; s += v[i]; }
    #pragma unroll
    for (int o = 16; o > 0; o >>= 1) s += __shfl_xor_sync(0xffffffffu, s, o);
    if ((t & 31) == 0) sh[t >> 5] = s;
    __syncthreads();
    float mean = (sh[0]+sh[1]+sh[2]+sh[3]+sh[4]+sh[5]+sh[6]+sh[7]) * (1.f/HH);
    __syncthreads();
    float sq = 0.f;
    #pragma unroll
    for (int i = 0; i < 8; i++) { float d = v[i]-mean; sq += d*d; }
    #pragma unroll
    for (int o = 16; o > 0; o >>= 1) sq += __shfl_xor_sync(0xffffffffu, sq, o);
    if ((t & 31) == 0) sh[t >> 5] = sq;
    __syncthreads();
    float rstd = rsqrtf((sh[0]+sh[1]+sh[2]+sh[3]+sh[4]+sh[5]+sh[6]+sh[7]) * (1.f/HH) + 1e-5f);
    long base = row * (long)HH;
    #pragma unroll
    for (int i = 0; i < 8; i++) {
        int c = t + i*256;
        float y = (v[i]-mean)*rstd*g[c] + b[c];
        if (of) of[base + c] = y;
        __nv_bfloat16 h, l; bsplit(y, h, l);
        oh[base + c] = h; ol[base + c] = l;
    }
}

__global__ void l2norm_kernel(const float* __restrict__ in, float* __restrict__ out)
{
    __shared__ float sh[8];
    long row = blockIdx.x;
    const float* x = in + row * (long)HH;
    int t = threadIdx.x;
    float v[8];
    float sq = 0.f;
    #pragma unroll
    for (int i = 0; i < 8; i++) { v[i] = x[t + i*256]; sq += v[i]*v[i]; }
    #pragma unroll
    for (int o = 16; o > 0; o >>= 1) sq += __shfl_xor_sync(0xffffffffu, sq, o);
    if ((t & 31) == 0) sh[t >> 5] = sq;
    __syncthreads();
    float tot = sh[0]+sh[1]+sh[2]+sh[3]+sh[4]+sh[5]+sh[6]+sh[7];
    float inv = 1.f / fmaxf(sqrtf(tot), 1e-12f);
    float* orow = out + row * (long)HH;
    #pragma unroll
    for (int i = 0; i < 8; i++) { int c = t + i*256; orow[c] = v[i]*inv; }
}

// softmax over rows of 512 -> bf16 hi/lo
__global__ void softmax_split(const float* __restrict__ s,
                              __nv_bfloat16* __restrict__ oh,
                              __nv_bfloat16* __restrict__ ol)
{
    long warp = ((long)blockIdx.x * blockDim.x + threadIdx.x) >> 5;
    int lane = threadIdx.x & 31;
    if (warp >= (long)NSROWS) return;
    const float* row = s + warp * (long)SS;
    float vals[16];
    float mx = -1e30f;
    #pragma unroll
    for (int i = 0; i < 16; i++) { vals[i] = row[lane + i*32]; mx = fmaxf(mx, vals[i]); }
    #pragma unroll
    for (int o = 16; o > 0; o >>= 1) mx = fmaxf(mx, __shfl_xor_sync(0xffffffffu, mx, o));
    float sum = 0.f;
    #pragma unroll
    for (int i = 0; i < 16; i++) { vals[i] = __expf(vals[i]-mx); sum += vals[i]; }
    #pragma unroll
    for (int o = 16; o > 0; o >>= 1) sum += __shfl_xor_sync(0xffffffffu, sum, o);
    float inv = 1.f / sum;
    long base = warp * (long)SS;
    #pragma unroll
    for (int i = 0; i < 16; i++) {
        float y = vals[i]*inv;
        __nv_bfloat16 h, l; bsplit(y, h, l);
        oh[base + lane + i*32] = h; ol[base + lane + i*32] = l;
    }
}

// transpose V [s,d] -> Vt [d,s] per head (bf16 hi/lo in, hi/lo out)
__global__ void vtrans_kernel(const __nv_bfloat16* __restrict__ qh,
                              const __nv_bfloat16* __restrict__ ql,
                              __nv_bfloat16* __restrict__ vh,
                              __nv_bfloat16* __restrict__ vl)
{
    __shared__ uint32_t tile[32][33];
    int bh = blockIdx.z;
    int b = bh >> 3, h = bh & 7;
    int s0 = blockIdx.x * 32, d0 = blockIdx.y * 32;
    int tx = threadIdx.x, ty = threadIdx.y;     // (32,8)
    long ibase = (long)b*QSTR + 2*HH + (long)h*HD;
    #pragma unroll
    for (int r = 0; r < 32; r += 8) {
        long idx = ibase + (long)(s0+ty+r)*H3 + d0+tx;
        uint32_t u = ((uint32_t)__bfloat16_as_ushort(qh[idx]) << 16)
                   |  (uint32_t)__bfloat16_as_ushort(ql[idx]);
        tile[ty+r][tx] = u;
    }
    __syncthreads();
    long obase = (long)bh * VTS;
    #pragma unroll
    for (int r = 0; r < 32; r += 8) {
        uint32_t u = tile[tx][ty+r];
        long o = obase + (long)(d0+ty+r)*SS + s0+tx;
        vh[o] = __ushort_as_bfloat16((unsigned short)(u >> 16));
        vl[o] = __ushort_as_bfloat16((unsigned short)(u & 0xffff));
    }
}

// ---------------- mma.sync bf16-split GEMM -------------------------------
// C = act( alpha*(A@B^T) + bias ) (+R).  A=[M,K], B=[N,K], both K-major bf16
// hi/lo pairs. CTA tile 128x128, 8 warps of 64x32, K chunk 64, 2-stage
// cp.async. OMODE 0: fp32 C; 1: bf16 hi/lo C.
#define STG_SZ 65536
#define SM_AH 0
#define SM_AL 16384
#define SM_BH 32768
#define SM_BL 49152
#define SMEMSZ (2*STG_SZ)

template<int ACT, bool RESID, int OMODE>
__global__ void __launch_bounds__(256, 1) tc_gemm(
    const __nv_bfloat16* __restrict__ Ah, const __nv_bfloat16* __restrict__ Al,
    const __nv_bfloat16* __restrict__ Bh, const __nv_bfloat16* __restrict__ Bl,
    const float* __restrict__ bias, const float* __restrict__ Rr,
    float* __restrict__ Cf,
    __nv_bfloat16* __restrict__ Ch, __nv_bfloat16* __restrict__ Cl,
    int K, int lda, int ldb, int ldc,
    long offA1, long offA2, long offB1, long offB2, long offC1, long offC2,
    float alpha)
{
    extern __shared__ char smem[];
    uint32_t sb = (uint32_t)__cvta_generic_to_shared(smem);
    int tid = threadIdx.x;
    int z = blockIdx.z, zb = z >> 3, zh = z & 7;
    long ash = zb*offA1 + zh*offA2;
    long bsh = zb*offB1 + zh*offB2;
    long csh = zb*offC1 + zh*offC2;
    Ah += ash; Al += ash; Bh += bsh; Bl += bsh;
    long m0 = (long)blockIdx.y * 128;
    long n0 = (long)blockIdx.x * 128;

    int l = tid & 31, w = tid >> 5;
    int wm = w & 1, wn = w >> 1;

    // ldmatrix base offsets (swizzle: byte = row*128 + (kb ^ ((row&7)<<4)))
    uint32_t a_off[4], b_off[2];
    #pragma unroll
    for (int mi = 0; mi < 4; mi++){
        int row = wm*64 + mi*16 + (l & 15);
        a_off[mi] = row*128 + (((l >> 4) << 4) ^ ((row & 7) << 4));
    }
    #pragma unroll
    for (int nj = 0; nj < 2; nj++){
        int row = wn*32 + nj*16 + (l & 7) + ((l & 16) ? 8 : 0);
        b_off[nj] = row*128 + ((((l >> 3) & 1) << 4) ^ ((row & 7) << 4));
    }

    float acc[4][4][4];
    #pragma unroll
    for (int a = 0; a < 4; a++)
        #pragma unroll
        for (int b = 0; b < 4; b++)
            #pragma unroll
            for (int c = 0; c < 4; c++) acc[a][b][c] = 0.f;

    const int NC = K >> 6;
    auto load_chunk = [&](int st, int kc){
        uint32_t base = sb + st*STG_SZ;
        long k0 = (long)kc << 6;
        #pragma unroll
        for (int i = 0; i < 4; i++){
            int task = tid + i*256;
            int row = task >> 3, seg = task & 7;
            uint32_t so = row*128 + ((seg*16) ^ ((row & 7) << 4));
            long ga = (m0 + row) * (long)lda + k0 + seg*8;
            long gb = (n0 + row) * (long)ldb + k0 + seg*8;
            cpa16(base + SM_AH + so, Ah + ga);
            cpa16(base + SM_AL + so, Al + ga);
            cpa16(base + SM_BH + so, Bh + gb);
            cpa16(base + SM_BL + so, Bl + gb);
        }
        asm volatile("cp.async.commit_group;\n" ::: "memory");
    };

    load_chunk(0, 0);
    for (int c = 0; c < NC; c++){
        if (c + 1 < NC){
            load_chunk((c+1)&1, c+1);
            asm volatile("cp.async.wait_group 1;\n" ::: "memory");
        } else {
            asm volatile("cp.async.wait_group 0;\n" ::: "memory");
        }
        __syncthreads();
        uint32_t bAh = sb + (c&1)*STG_SZ + SM_AH;
        uint32_t bAl = sb + (c&1)*STG_SZ + SM_AL;
        uint32_t bBh = sb + (c&1)*STG_SZ + SM_BH;
        uint32_t bBl = sb + (c&1)*STG_SZ + SM_BL;
        #pragma unroll
        for (int ks = 0; ks < 4; ks++){
            uint32_t kx = (uint32_t)ks << 5;
            uint32_t ahf[4][4], alf[4][4], bhf[2][4], blf[2][4];
            #pragma unroll
            for (int mi = 0; mi < 4; mi++){
                ldsm4(bAh + (a_off[mi] ^ kx), ahf[mi]);
                ldsm4(bAl + (a_off[mi] ^ kx), alf[mi]);
            }
            #pragma unroll
            for (int nj = 0; nj < 2; nj++){
                ldsm4(bBh + (b_off[nj] ^ kx), bhf[nj]);
                ldsm4(bBl + (b_off[nj] ^ kx), blf[nj]);
            }
            #pragma unroll
            for (int mi = 0; mi < 4; mi++)
                #pragma unroll
                for (int nj = 0; nj < 4; nj++){
                    const uint32_t* b2h = &bhf[nj>>1][(nj&1)*2];
                    const uint32_t* b2l = &blf[nj>>1][(nj&1)*2];
                    mma16816(acc[mi][nj], ahf[mi], b2h);
                    mma16816(acc[mi][nj], alf[mi], b2h);
                    mma16816(acc[mi][nj], ahf[mi], b2l);
                }
        }
        __syncthreads();
    }

    // epilogue
    int r0 = (int)m0 + wm*64 + (l >> 2);
    int c0 = (int)n0 + wn*32 + 2*(l & 3);
    #pragma unroll
    for (int mi = 0; mi < 4; mi++){
        #pragma unroll
        for (int half = 0; half < 2; half++){
            long row = r0 + mi*16 + half*8;
            #pragma unroll
            for (int nj = 0; nj < 4; nj++){
                int cc = c0 + nj*8;
                long o = csh + row*(long)ldc + cc;
                float v0 = acc[mi][nj][half*2+0] * alpha;
                float v1 = acc[mi][nj][half*2+1] * alpha;
                if (bias){ v0 += bias[cc]; v1 += bias[cc+1]; }
                if (ACT == 1){
                    v0 = 0.5f*v0*(1.f + erff(v0*0.70710678118654752f));
                    v1 = 0.5f*v1*(1.f + erff(v1*0.70710678118654752f));
                } else if (ACT == 2){
                    v0 = fmaxf(v0, 0.f); v1 = fmaxf(v1, 0.f);
                }
                if (RESID){
                    const float* rp = Rr + o;
                    v0 += rp[0]; v1 += rp[1];
                }
                if (OMODE == 0){
                    *(float2*)(Cf + o) = make_float2(v0, v1);
                } else {
                    __nv_bfloat16 h0,l0,h1,l1;
                    bsplit(v0,h0,l0); bsplit(v1,h1,l1);
                    *(__nv_bfloat162*)(Ch + o) = __nv_bfloat162(h0,h1);
                    *(__nv_bfloat162*)(Cl + o) = __nv_bfloat162(l0,l1);
                }
            }
        }
    }
}

// ---------------- host orchestration -------------------------------------
extern "C" void kernel_launch(void* const* d_in, const int* in_sizes, int n_in,
                              void* d_out, int out_size)
{
    (void)in_sizes; (void)n_in; (void)out_size;
    const float* emb  = (const float*)d_in[0];
    const int*   tidx = (const int*)  d_in[1];
    const float* pe   = (const float*)d_in[2];
    const float* inw  = (const float*)d_in[3];
    const float* inb  = (const float*)d_in[4];
    const float* ow   = (const float*)d_in[5];
    const float* ob   = (const float*)d_in[6];
    const float* ln1g = (const float*)d_in[7];
    const float* ln1b = (const float*)d_in[8];
    const float* f1w  = (const float*)d_in[9];
    const float* f1b  = (const float*)d_in[10];
    const float* f2w  = (const float*)d_in[11];
    const float* f2b  = (const float*)d_in[12];
    const float* ln2g = (const float*)d_in[13];
    const float* ln2b = (const float*)d_in[14];
    const float* te1w = (const float*)d_in[15];
    const float* te1b = (const float*)d_in[16];
    const float* te2w = (const float*)d_in[17];
    const float* te2b = (const float*)d_in[18];
    const float* pr1w = (const float*)d_in[19];
    const float* pr1b = (const float*)d_in[20];
    const float* pr2w = (const float*)d_in[21];
    const float* pr2b = (const float*)d_in[22];
    float* out = (float*)d_out;

    float *sc,*t1,*t2,*h1;
    __nv_bfloat16 *pAh,*pAl,*pBh,*pBl,*vh,*vl,*wh,*wl;
    cudaGetSymbolAddress((void**)&sc,  g_sc);
    cudaGetSymbolAddress((void**)&t1,  g_t1);
    cudaGetSymbolAddress((void**)&t2,  g_t2);
    cudaGetSymbolAddress((void**)&h1,  g_h1);
    cudaGetSymbolAddress((void**)&pAh, g_pAh);
    cudaGetSymbolAddress((void**)&pAl, g_pAl);
    cudaGetSymbolAddress((void**)&pBh, g_pBh);
    cudaGetSymbolAddress((void**)&pBl, g_pBl);
    cudaGetSymbolAddress((void**)&vh,  g_vh);
    cudaGetSymbolAddress((void**)&vl,  g_vl);
    cudaGetSymbolAddress((void**)&wh,  g_wh);
    cudaGetSymbolAddress((void**)&wl,  g_wl);

    cudaFuncSetAttribute(tc_gemm<0,false,1>, cudaFuncAttributeMaxDynamicSharedMemorySize, SMEMSZ);
    cudaFuncSetAttribute(tc_gemm<0,false,0>, cudaFuncAttributeMaxDynamicSharedMemorySize, SMEMSZ);
    cudaFuncSetAttribute(tc_gemm<0,true ,0>, cudaFuncAttributeMaxDynamicSharedMemorySize, SMEMSZ);
    cudaFuncSetAttribute(tc_gemm<1,false,1>, cudaFuncAttributeMaxDynamicSharedMemorySize, SMEMSZ);
    cudaFuncSetAttribute(tc_gemm<2,false,1>, cudaFuncAttributeMaxDynamicSharedMemorySize, SMEMSZ);

    auto wsplit = [&](const float* src, long n){
        split_kernel<<<(unsigned)((n/4 + 255) / 256), 256>>>(src, wh, wl, n/4);
    };

    // 1) x = emb + pe[idx]  -> poolB
    gather_pe_split<<<(MR*(HH/4) + 255)/256, 256>>>(emb, pe, tidx, pBh, pBl);

    // 2) qkv = x @ in_proj_w^T + b  -> poolA (hi/lo)
    wsplit(inw, (long)H3*HH);
    tc_gemm<0,false,1><<<dim3(H3/128, MR/128, 1), 256, SMEMSZ>>>(
        pBh, pBl, wh, wl, inb, 0, 0, pAh, pAl,
        HH, HH, HH, H3, 0,0,0,0,0,0, 1.f);

    // 3) scores = (Q@K^T)/16 -> fp32 sc   (batched over 256 heads)
    tc_gemm<0,false,0><<<dim3(SS/128, SS/128, NHEADS), 256, SMEMSZ>>>(
        pAh, pAl, pAh + HH, pAl + HH, 0, 0, sc, 0, 0,
        HD, H3, H3, SS, QSTR, HD, QSTR, HD, 8*SCH, SCH, 0.0625f);

    // 4) Vt transpose (from qkv hi/lo), softmax -> poolB
    vtrans_kernel<<<dim3(SS/32, HD/32, NHEADS), dim3(32,8)>>>(pAh, pAl, vh, vl);
    softmax_split<<<NSROWS/8, 256>>>(sc, pBh, pBl);

    // 5) o = A @ V -> poolA (hi/lo)
    tc_gemm<0,false,1><<<dim3(HD/128, SS/128, NHEADS), 256, SMEMSZ>>>(
        pBh, pBl, vh, vl, 0, 0, 0, pAh, pAl,
        SS, SS, SS, HH, 8*SCH, SCH, 8*VTS, VTS, (long)SS*HH, HD, 1.f);

    // 6) t1 = o @ out_proj_w^T + b + emb -> fp32
    wsplit(ow, (long)HH*HH);
    tc_gemm<0,true,0><<<dim3(HH/128, MR/128, 1), 256, SMEMSZ>>>(
        pAh, pAl, wh, wl, ob, emb, t1, 0, 0,
        HH, HH, HH, HH, 0,0,0,0,0,0, 1.f);

    // 7) h1 = LN(t1) -> fp32 (residual) + poolB (hi/lo)
    ln_split_kernel<<<MR, 256>>>(t1, ln1g, ln1b, h1, pBh, pBl);

    // 8) mid = gelu(h1 @ ffn_w1^T + b1) -> poolA (hi/lo)
    wsplit(f1w, (long)H4*HH);
    tc_gemm<1,false,1><<<dim3(H4/128, MR/128, 1), 256, SMEMSZ>>>(
        pBh, pBl, wh, wl, f1b, 0, 0, pAh, pAl,
        HH, HH, HH, H4, 0,0,0,0,0,0, 1.f);

    // 9) t2 = mid @ ffn_w2^T + b2 + h1 -> fp32
    wsplit(f2w, (long)HH*H4);
    tc_gemm<0,true,0><<<dim3(HH/128, MR/128, 1), 256, SMEMSZ>>>(
        pAh, pAl, wh, wl, f2b, h1, t2, 0, 0,
        H4, H4, H4, HH, 0,0,0,0,0,0, 1.f);

    // 10) h2 = LN(t2) -> poolB (hi/lo only)
    ln_split_kernel<<<MR, 256>>>(t2, ln2g, ln2b, 0, pBh, pBl);

    // 11) relu(h2 @ te_w1^T + b1) -> poolA
    wsplit(te1w, (long)HH*HH);
    tc_gemm<2,false,1><<<dim3(HH/128, MR/128, 1), 256, SMEMSZ>>>(
        pBh, pBl, wh, wl, te1b, 0, 0, pAh, pAl,
        HH, HH, HH, HH, 0,0,0,0,0,0, 1.f);

    // 12) te2 -> poolB
    wsplit(te2w, (long)HH*HH);
    tc_gemm<0,false,1><<<dim3(HH/128, MR/128, 1), 256, SMEMSZ>>>(
        pAh, pAl, wh, wl, te2b, 0, 0, pBh, pBl,
        HH, HH, HH, HH, 0,0,0,0,0,0, 1.f);

    // 13) relu(pr1) -> poolA
    wsplit(pr1w, (long)HH*HH);
    tc_gemm<2,false,1><<<dim3(HH/128, MR/128, 1), 256, SMEMSZ>>>(
        pBh, pBl, wh, wl, pr1b, 0, 0, pAh, pAl,
        HH, HH, HH, HH, 0,0,0,0,0,0, 1.f);

    // 14) pr2 -> fp32 t1
    wsplit(pr2w, (long)HH*HH);
    tc_gemm<0,false,0><<<dim3(HH/128, MR/128, 1), 256, SMEMSZ>>>(
        pAh, pAl, wh, wl, pr2b, 0, t1, 0, 0,
        HH, HH, HH, HH, 0,0,0,0,0,0, 1.f);

    // 15) out = pr / max(||pr||, 1e-12)
    l2norm_kernel<<<MR, 256>>>(t1, out);
}